// round 2
// baseline (speedup 1.0000x reference)
#include <cuda_runtime.h>
#include <cuda_bf16.h>
#include <stdint.h>

// Problem constants (fixed by the dataset instance)
constexpr int B    = 4;
constexpr int H    = 8;
constexpr int LQ   = 1024;
constexpr int DH   = 64;
constexpr int KLEN = 1024;
constexpr int LTOT = 1024;   // time_ids second dim
constexpr int TBL  = 33;     // 2*MAX_REL_POS + 1
constexpr int PAD  = 65;     // DH padded stride to avoid smem bank conflicts

__global__ __launch_bounds__(256)
void relpe_kernel(const float* __restrict__ q,
                  const float* __restrict__ table,
                  const int* __restrict__ tids,   // int32! (jax silently downcasts int64)
                  float* __restrict__ out)
{
    const int blk  = blockIdx.x;        // 0 .. B*LQ-1
    const int b    = blk / LQ;
    const int qpos = blk % LQ;
    const int tid  = threadIdx.x;

    __shared__ float qsh[H * PAD];          // 8 x 64 query slab (padded)
    __shared__ float tsh[TBL * PAD];        // 33 x 64 table (padded)
    __shared__ float S[H][TBL];             // 264 precomputed dots
    __shared__ int   tk[KLEN];              // time ids
    __shared__ unsigned char idx_sh[KLEN];  // gather indices

    // ---- load query slab: q[b, h, qpos, d] ----
    for (int i = tid; i < H * DH; i += 256) {
        int h = i >> 6, d = i & 63;
        qsh[h * PAD + d] = q[(((size_t)b * H + h) * LQ + qpos) * DH + d];
    }
    // ---- load rel_table ----
    for (int i = tid; i < TBL * DH; i += 256) {
        int j = i >> 6, d = i & 63;
        tsh[j * PAD + d] = table[i];
    }
    // ---- load time ids for this batch ----
    for (int k = tid; k < KLEN; k += 256) {
        tk[k] = tids[(size_t)b * LTOT + k];
    }
    __syncthreads();

    // ---- idx[k] = clip(ts[k] - ts[qpos], -16, 16) + 16 ----
    const int tq = tk[qpos];
    for (int k = tid; k < KLEN; k += 256) {
        int rel = tk[k] - tq;
        rel = rel < -16 ? -16 : (rel > 16 ? 16 : rel);
        idx_sh[k] = (unsigned char)(rel + 16);
    }

    // ---- S[h][j] = dot(qsh[h,:], tsh[j,:]) ----
    for (int i = tid; i < H * TBL; i += 256) {
        int h = i / TBL, j = i - h * TBL;
        const float* qa = &qsh[h * PAD];
        const float* ta = &tsh[j * PAD];
        float acc = 0.f;
        #pragma unroll
        for (int d = 0; d < DH; d += 4) {
            acc += qa[d]     * ta[d];
            acc += qa[d + 1] * ta[d + 1];
            acc += qa[d + 2] * ta[d + 2];
            acc += qa[d + 3] * ta[d + 3];
        }
        S[h][j] = acc;
    }
    __syncthreads();

    // ---- stream output: out[b, h, qpos, k] = S[h][idx[k]] ----
    // 256 threads x float4 = 1024 k per h, fully coalesced.
    const int k0 = tid * 4;
    const unsigned char i0 = idx_sh[k0];
    const unsigned char i1 = idx_sh[k0 + 1];
    const unsigned char i2 = idx_sh[k0 + 2];
    const unsigned char i3 = idx_sh[k0 + 3];
    #pragma unroll
    for (int h = 0; h < H; h++) {
        float4 v;
        v.x = S[h][i0];
        v.y = S[h][i1];
        v.z = S[h][i2];
        v.w = S[h][i3];
        size_t base = (((size_t)b * H + h) * LQ + qpos) * KLEN;
        reinterpret_cast<float4*>(out + base)[tid] = v;
    }
}

extern "C" void kernel_launch(void* const* d_in, const int* in_sizes, int n_in,
                              void* d_out, int out_size)
{
    const float* q     = (const float*)d_in[0];
    const float* table = (const float*)d_in[1];
    const int*   tids  = (const int*)d_in[2];
    float*       out   = (float*)d_out;

    relpe_kernel<<<B * LQ, 256>>>(q, table, tids, out);
}

// round 3
// speedup vs baseline: 1.4299x; 1.4299x over previous
#include <cuda_runtime.h>
#include <cuda_bf16.h>
#include <stdint.h>

constexpr int B    = 4;
constexpr int H    = 8;
constexpr int LQ   = 1024;
constexpr int DH   = 64;
constexpr int KLEN = 1024;
constexpr int TBL  = 33;     // 2*MAX_REL_POS + 1

// Scratch: P[b][q][j][h]  (4*1024*33*8 floats = 4.3 MB)
__device__ float Pbuf[B * LQ * TBL * H];

__device__ __forceinline__ void ffma2(unsigned long long& acc,
                                      unsigned long long a,
                                      unsigned long long b)
{
    asm("fma.rn.f32x2 %0, %1, %2, %0;" : "+l"(acc) : "l"(a), "l"(b));
}
__device__ __forceinline__ float f2lo(unsigned long long v) {
    return __uint_as_float((unsigned)v);
}
__device__ __forceinline__ float f2hi(unsigned long long v) {
    return __uint_as_float((unsigned)(v >> 32));
}

// ---------------------------------------------------------------------------
// Kernel 1: P[b,q,j,h] = dot(query[b,h,q,:], table[j,:])
// One thread per (b,q,h) row. q-vector lives in registers (32 packed f32x2).
// j/d loops are warp-uniform -> all table LDS are broadcasts (conflict-free,
// 1 wavefront each). FMA via packed fma.rn.f32x2.
// ---------------------------------------------------------------------------
__global__ __launch_bounds__(256)
void proj_kernel(const float* __restrict__ q,
                 const float* __restrict__ table)
{
    __shared__ ulonglong2 tsh[TBL * 16];   // 33 rows x 64 floats (as 16 x ull2)

    const int tid = threadIdx.x;

    // stage table: 33*64 floats = 528 ulonglong2
    {
        const ulonglong2* t2 = reinterpret_cast<const ulonglong2*>(table);
        for (int i = tid; i < TBL * 16; i += 256) tsh[i] = t2[i];
    }

    const int r    = blockIdx.x * 256 + tid;   // 0 .. 32767
    const int h    = r & 7;
    const int qpos = (r >> 3) & (LQ - 1);
    const int b    = r >> 13;

    // load q row into registers as 32 packed f32x2
    unsigned long long qp[32];
    {
        const ulonglong2* qr = reinterpret_cast<const ulonglong2*>(
            q + ((((size_t)b * H + h) * LQ + qpos) * DH));
        #pragma unroll
        for (int c = 0; c < 16; c++) {
            ulonglong2 v = qr[c];
            qp[2 * c]     = v.x;
            qp[2 * c + 1] = v.y;
        }
    }
    __syncthreads();

    float* pout = Pbuf + ((size_t)b * LQ + qpos) * (TBL * H) + h;

    for (int j = 0; j < TBL; j++) {
        unsigned long long a01 = 0ull, a23 = 0ull;
        #pragma unroll
        for (int c = 0; c < 16; c++) {
            ulonglong2 t = tsh[j * 16 + c];   // broadcast across warp
            ffma2(a01, qp[2 * c],     t.x);
            ffma2(a23, qp[2 * c + 1], t.y);
        }
        float s = (f2lo(a01) + f2hi(a01)) + (f2lo(a23) + f2hi(a23));
        pout[j * H] = s;
    }
}

// ---------------------------------------------------------------------------
// Kernel 2: out[b,h,q,k] = P[b,q, idx(b,q,k), h]
// One block per (b,q). idx computed in registers from an int4 load of
// time_ids. P slab staged in smem [j][h] so each gathered row is 2x LDS.128.
// 8 coalesced float4 stores per thread.
// ---------------------------------------------------------------------------
__global__ __launch_bounds__(256)
void gather_kernel(const int* __restrict__ tids,
                   float* __restrict__ out)
{
    const int blk  = blockIdx.x;        // 0 .. B*LQ-1
    const int b    = blk >> 10;
    const int qpos = blk & (LQ - 1);
    const int tid  = threadIdx.x;

    __shared__ float4 st[TBL * 2];      // P slab, [j] -> 2 float4 (8 h values)

    if (tid < TBL * 2) {
        st[tid] = reinterpret_cast<const float4*>(
            Pbuf + (size_t)blk * (TBL * H))[tid];
    }

    // idx for this thread's 4 k values, straight from registers
    const int tq = tids[b * KLEN + qpos];
    int4 t4 = reinterpret_cast<const int4*>(tids + (size_t)b * KLEN)[tid];

    int i0 = t4.x - tq; i0 = i0 < -16 ? -16 : (i0 > 16 ? 16 : i0); i0 += 16;
    int i1 = t4.y - tq; i1 = i1 < -16 ? -16 : (i1 > 16 ? 16 : i1); i1 += 16;
    int i2 = t4.z - tq; i2 = i2 < -16 ? -16 : (i2 > 16 ? 16 : i2); i2 += 16;
    int i3 = t4.w - tq; i3 = i3 < -16 ? -16 : (i3 > 16 ? 16 : i3); i3 += 16;

    __syncthreads();

    // gather 4 rows x 8 h into registers
    float r[4][8];
    {
        int ii[4] = {i0, i1, i2, i3};
        #pragma unroll
        for (int m = 0; m < 4; m++) {
            float4 a = st[2 * ii[m]];
            float4 c = st[2 * ii[m] + 1];
            r[m][0] = a.x; r[m][1] = a.y; r[m][2] = a.z; r[m][3] = a.w;
            r[m][4] = c.x; r[m][5] = c.y; r[m][6] = c.z; r[m][7] = c.w;
        }
    }

    // stream: for each h, one coalesced float4 store
    #pragma unroll
    for (int h = 0; h < H; h++) {
        float4 v;
        v.x = r[0][h]; v.y = r[1][h]; v.z = r[2][h]; v.w = r[3][h];
        float4* o4 = reinterpret_cast<float4*>(
            out + ((((size_t)b * H + h) * LQ + qpos) * KLEN));
        o4[tid] = v;
    }
}

extern "C" void kernel_launch(void* const* d_in, const int* in_sizes, int n_in,
                              void* d_out, int out_size)
{
    const float* q     = (const float*)d_in[0];
    const float* table = (const float*)d_in[1];
    const int*   tids  = (const int*)d_in[2];
    float*       out   = (float*)d_out;

    proj_kernel<<<(B * H * LQ) / 256, 256>>>(q, table);
    gather_kernel<<<B * LQ, 256>>>(tids, out);
}